// round 16
// baseline (speedup 1.0000x reference)
#include <cuda_runtime.h>
#include <cstdint>

// LIF recurrence: T=64 steps, B*N = 524288 independent lanes.
//   h = v + (x - v) * 0.5 ; s = (h>=1) ; v = s ? 0 : h
// Pure HBM stream: 134 MB in + 134 MB out (compulsory, zero reuse).
//
// Confirmed winner geometry: float4, unroll 8, 128-thr blocks (1024
// CTAs, single wave). R13=45.8us, R15 replication=46.2us vs 47.4-48.7
// for everything else — the unroll-8 effect is real (issue overhead /
// clock residency in the sustained loop; invisible to ncu one-shot).
// R16 delta: strip residual per-step overhead inside the body —
//  (a) no prefetch var, no t+1<T predicate (both pointers __restrict,
//      ptxas hoists the 8 independent loads itself),
//  (b) pointer-bump addressing (IADD per step) instead of per-access
//      64-bit IMAD index chains.

static constexpr int T = 64;

__global__ void __launch_bounds__(128) lif_kernel(const float4* __restrict__ x,
                                                  float4* __restrict__ out,
                                                  int lanes4)  // B*N/4 per timestep
{
    int i = blockIdx.x * blockDim.x + threadIdx.x;
    if (i >= lanes4) return;

    const float4* __restrict__ px = x + i;
    float4* __restrict__ po = out + i;

    float4 v = make_float4(0.f, 0.f, 0.f, 0.f);

    #pragma unroll 8
    for (int t = 0; t < T; ++t) {
        float4 xt = *px;
        px += lanes4;

        float4 h, s;
        h.x = v.x + (xt.x - v.x) * 0.5f;
        h.y = v.y + (xt.y - v.y) * 0.5f;
        h.z = v.z + (xt.z - v.z) * 0.5f;
        h.w = v.w + (xt.w - v.w) * 0.5f;

        s.x = (h.x >= 1.0f) ? 1.0f : 0.0f;
        s.y = (h.y >= 1.0f) ? 1.0f : 0.0f;
        s.z = (h.z >= 1.0f) ? 1.0f : 0.0f;
        s.w = (h.w >= 1.0f) ? 1.0f : 0.0f;

        v.x = (h.x >= 1.0f) ? 0.0f : h.x;
        v.y = (h.y >= 1.0f) ? 0.0f : h.y;
        v.z = (h.z >= 1.0f) ? 0.0f : h.z;
        v.w = (h.w >= 1.0f) ? 0.0f : h.w;

        *po = s;
        po += lanes4;
    }
}

extern "C" void kernel_launch(void* const* d_in, const int* in_sizes, int n_in,
                              void* d_out, int out_size)
{
    const float4* x = (const float4*)d_in[0];
    float4* out = (float4*)d_out;

    int total = in_sizes[0];          // T * B * N
    int lanes = total / T;            // 524288
    int lanes4 = lanes / 4;           // 131072

    int threads = 128;                // 1024 CTAs -> single wave, even balance
    int blocks = (lanes4 + threads - 1) / threads;
    lif_kernel<<<blocks, threads>>>(x, out, lanes4);
}

// round 17
// speedup vs baseline: 1.0149x; 1.0149x over previous
#include <cuda_runtime.h>
#include <cstdint>

// LIF recurrence: T=64 steps, B*N = 524288 independent lanes.
//   h = v + (x - v) * 0.5 ; s = (h>=1) ; v = s ? 0 : h
// Pure HBM stream: 134 MB in + 134 MB out (compulsory, zero reuse).
//
// Confirmed best structure (R13/R15: 45.8/46.2us vs >=47.4 for all
// others): float4, DISTANCE-1 SCALAR PREFETCH (load-bearing — removing
// it in R16 regressed to 47.9), indexed addressing, unroll 8.
// R17 delta: 64-thread blocks (2048 CTAs, 13.8/SM) — at unroll 4 this
// geometry gave the session-best ncu one-shot (36.54us) and was
// harness-neutral; orthogonal to the unroll-8 issue-overhead win, so
// this is the last untested cell of the matrix.

static constexpr int T = 64;

__global__ void __launch_bounds__(64) lif_kernel(const float4* __restrict__ x,
                                                 float4* __restrict__ out,
                                                 int lanes4)  // B*N/4 per timestep
{
    int i = blockIdx.x * blockDim.x + threadIdx.x;
    if (i >= lanes4) return;

    float4 v = make_float4(0.f, 0.f, 0.f, 0.f);

    // distance-1 scalar prefetch (load-bearing; do not remove)
    float4 xt = x[i];

    #pragma unroll 8
    for (int t = 0; t < T; ++t) {
        float4 xnext;
        if (t + 1 < T) xnext = x[(size_t)(t + 1) * lanes4 + i];

        float4 h, s;
        h.x = v.x + (xt.x - v.x) * 0.5f;
        h.y = v.y + (xt.y - v.y) * 0.5f;
        h.z = v.z + (xt.z - v.z) * 0.5f;
        h.w = v.w + (xt.w - v.w) * 0.5f;

        s.x = (h.x >= 1.0f) ? 1.0f : 0.0f;
        s.y = (h.y >= 1.0f) ? 1.0f : 0.0f;
        s.z = (h.z >= 1.0f) ? 1.0f : 0.0f;
        s.w = (h.w >= 1.0f) ? 1.0f : 0.0f;

        v.x = (h.x >= 1.0f) ? 0.0f : h.x;
        v.y = (h.y >= 1.0f) ? 0.0f : h.y;
        v.z = (h.z >= 1.0f) ? 0.0f : h.z;
        v.w = (h.w >= 1.0f) ? 0.0f : h.w;

        out[(size_t)t * lanes4 + i] = s;

        xt = xnext;
    }
}

extern "C" void kernel_launch(void* const* d_in, const int* in_sizes, int n_in,
                              void* d_out, int out_size)
{
    const float4* x = (const float4*)d_in[0];
    float4* out = (float4*)d_out;

    int total = in_sizes[0];          // T * B * N
    int lanes = total / T;            // 524288
    int lanes4 = lanes / 4;           // 131072

    int threads = 64;                 // 2048 CTAs -> finest even balance
    int blocks = (lanes4 + threads - 1) / threads;
    lif_kernel<<<blocks, threads>>>(x, out, lanes4);
}